// round 15
// baseline (speedup 1.0000x reference)
#include <cuda_runtime.h>
#include <cuda_fp16.h>
#include <cstdint>

// Problem constants
#define AA   128
#define SPN  1024
#define FF   128
#define HH   4
#define DD   128
#define NNW  512
#define RR   131072

// ------------------------------------------------------------------
// Scratch (static device globals — allocation-rule safe)
// ------------------------------------------------------------------
__device__ __align__(16) __half g_wth[NNW * FF];                      // W_r^T fp16: [n_g][f]
__device__ __align__(16) float g_sl[RR * HH];
__device__ __align__(16) float g_sr[RR * HH];
__device__ __align__(16) float g_ul[FF * HH];
__device__ __align__(16) float g_ur[FF * HH];

// ------------------------------------------------------------------
// PTX helpers
// ------------------------------------------------------------------
__device__ __forceinline__ uint32_t smem_u32(const void* p) {
    uint32_t a;
    asm("{ .reg .u64 t; cvta.to.shared.u64 t, %1; cvt.u32.u64 %0, t; }" : "=r"(a) : "l"(p));
    return a;
}
__device__ __forceinline__ void ldsm4(uint32_t* r, uint32_t addr) {
    asm volatile("ldmatrix.sync.aligned.m8n8.x4.shared.b16 {%0,%1,%2,%3}, [%4];"
                 : "=r"(r[0]), "=r"(r[1]), "=r"(r[2]), "=r"(r[3]) : "r"(addr));
}
__device__ __forceinline__ void ldsm2(uint32_t* r, uint32_t addr) {
    asm volatile("ldmatrix.sync.aligned.m8n8.x2.shared.b16 {%0,%1}, [%2];"
                 : "=r"(r[0]), "=r"(r[1]) : "r"(addr));
}
__device__ __forceinline__ void mma16816(float* c, const uint32_t* a, const uint32_t* b) {
    asm volatile("mma.sync.aligned.m16n8k16.row.col.f32.f16.f16.f32 "
                 "{%0,%1,%2,%3}, {%4,%5,%6,%7}, {%8,%9}, {%0,%1,%2,%3};"
                 : "+f"(c[0]), "+f"(c[1]), "+f"(c[2]), "+f"(c[3])
                 : "r"(a[0]), "r"(a[1]), "r"(a[2]), "r"(a[3]), "r"(b[0]), "r"(b[1]));
}
__device__ __forceinline__ void cpasync16(uint32_t dst, const void* src) {
    asm volatile("cp.async.cg.shared.global [%0], [%1], 16;" :: "r"(dst), "l"(src));
}
__device__ __forceinline__ void cpcommit() { asm volatile("cp.async.commit_group;"); }
template<int N> __device__ __forceinline__ void cpwait() {
    asm volatile("cp.async.wait_group %0;" :: "n"(N));
}
__device__ __forceinline__ uint32_t h2_u32(__half2 v) {
    return *reinterpret_cast<uint32_t*>(&v);
}
// swizzled address of 16B chunk ch (0..15) in row r (256B rows, XOR row&7)
__device__ __forceinline__ uint32_t sw16(int r, int ch) {
    return (uint32_t)(r * 256 + ((ch ^ (r & 7)) << 4));
}
__device__ __forceinline__ float pick4(float4 f, int hh) {
    return hh == 0 ? f.x : hh == 1 ? f.y : hh == 2 ? f.z : f.w;
}

// ============================================================
// K1: fold w_attn into W_l / W_r per head
// ============================================================
__global__ void k_u(const float* __restrict__ Wl, const float* __restrict__ Wr,
                    const float* __restrict__ wa) {
    __shared__ float w[2 * DD];
    int t = threadIdx.x;               // 512 threads
    if (t < 2 * DD) w[t] = wa[t];
    __syncthreads();
    int f = t >> 2, hh = t & 3;
    const float* pl = Wl + (size_t)f * NNW + hh * DD;
    const float* pr = Wr + (size_t)f * NNW + hh * DD;
    float sl = 0.f, sr = 0.f;
#pragma unroll 4
    for (int d = 0; d < DD; d++) {
        sl = fmaf(pl[d], w[d], sl);
        sr = fmaf(pr[d], w[DD + d], sr);
    }
    g_ul[f * HH + hh] = sl;
    g_ur[f * HH + hh] = sr;
}

// ============================================================
// K2: s_l / s_r  (one warp per row) — exact fp32
// ============================================================
__global__ void __launch_bounds__(256) k_s(const float* __restrict__ h) {
    __shared__ float ul[FF * HH], ur[FF * HH];
    int t = threadIdx.x;
    for (int q = t; q < FF * HH; q += 256) { ul[q] = g_ul[q]; ur[q] = g_ur[q]; }
    __syncthreads();
    int warp = t >> 5, lane = t & 31;
    int rid = blockIdx.x * 8 + warp;
    int sp = rid >> 7, a = rid & 127;
    const float* hr = h + ((size_t)a * SPN + sp) * FF;
    float hv[4];
#pragma unroll
    for (int u = 0; u < 4; u++) hv[u] = hr[lane + 32 * u];
    float accl[4] = {0, 0, 0, 0}, accr[4] = {0, 0, 0, 0};
#pragma unroll
    for (int u = 0; u < 4; u++) {
        int f = lane + 32 * u;
#pragma unroll
        for (int hh = 0; hh < 4; hh++) {
            accl[hh] = fmaf(hv[u], ul[f * 4 + hh], accl[hh]);
            accr[hh] = fmaf(hv[u], ur[f * 4 + hh], accr[hh]);
        }
    }
#pragma unroll
    for (int hh = 0; hh < 4; hh++) {
        for (int o = 16; o; o >>= 1) {
            accl[hh] += __shfl_xor_sync(0xffffffffu, accl[hh], o);
            accr[hh] += __shfl_xor_sync(0xffffffffu, accr[hh], o);
        }
    }
    if (lane == 0) {
        *(float4*)&g_sl[rid * 4] = make_float4(accl[0], accl[1], accl[2], accl[3]);
        *(float4*)&g_sr[rid * 4] = make_float4(accr[0], accr[1], accr[2], accr[3]);
    }
}

// ============================================================
// K3: transpose W_r to fp16: g_wth[n][f] = fp16(W_r[f][n])
// ============================================================
__global__ void __launch_bounds__(256) k_split_w(const float* __restrict__ Wr) {
    int t = blockIdx.x * 256 + threadIdx.x;            // < NNW*FF = 65536
    int f = t & 127, n = t >> 7;
    g_wth[t] = __float2half_rn(Wr[(size_t)f * NNW + n]);
}

// ============================================================
// K4: FUSED, warp-specialized. P warps (0-7): MMA1 g_h = W_h @ h^T.
//     C warps (8-15): softmax + MMA2 attn_res accumulation.
//     Pipeline: MMA2(h) overlaps MMA1(h+1); softmax overlaps MMA1(h0).
// ============================================================
// 7 swizzled planes, 256B row stride, 32KB each:
#define F_HT   0
#define F_W0   32768
#define F_W1   65536
#define F_G0   98304
#define F_G1   131072
#define F_A0   163840
#define F_A1   196608
#define F_SIZE 229376

// cp.async fill [128][128]-half tile into swizzled plane (256 threads)
__device__ __forceinline__ void fill_w_sw(uint32_t dbuf, const __half* src, int t) {
#pragma unroll
    for (int q = 0; q < 8; q++) {
        int idx = t + q * 256;            // 0..2047
        int r = idx >> 4, c = idx & 15;
        cpasync16(dbuf + sw16(r, c), src + r * 128 + c * 8);
    }
    cpcommit();
}

// one 128x128x128 tile GEMM: A rows strip base_m (2x16), B rows strip base_n (8x8)
__device__ __forceinline__ void mma_tile(uint32_t sbA, uint32_t sbB,
                                         float acc[2][8][4], int lane,
                                         int base_m, int base_n) {
#pragma unroll
    for (int ks = 0; ks < 8; ks++) {
        int kb = ks * 16;
        int chA = (kb >> 3) + (lane >> 4);
        int chB = (kb >> 3) + ((lane >> 3) & 1);
        uint32_t bh[8][2];
#pragma unroll
        for (int nt = 0; nt < 8; nt++) {
            int r = base_n + nt * 8 + (lane & 7);
            ldsm2(bh[nt], sbB + sw16(r, chB));
        }
#pragma unroll
        for (int mt = 0; mt < 2; mt++) {
            int r = base_m + mt * 16 + (lane & 15);
            uint32_t ah[4];
            ldsm4(ah, sbA + sw16(r, chA));
#pragma unroll
            for (int nt = 0; nt < 8; nt++) mma16816(acc[mt][nt], ah, bh[nt]);
        }
    }
}

// store MMA1 result to swizzled g plane (fp16)
__device__ __forceinline__ void store_g(char* smem, uint32_t plane,
                                        float acc[2][8][4], int lane, int wm, int wn) {
#pragma unroll
    for (int mt = 0; mt < 2; mt++) {
#pragma unroll
        for (int nt = 0; nt < 8; nt++) {
            int gm = wm * 32 + mt * 16 + (lane >> 2);
            int col = wn * 64 + nt * 8 + (lane & 3) * 2;
            uint32_t a0 = plane + (uint32_t)gm * 256 + (((col >> 3) ^ (gm & 7)) << 4) + (col & 7) * 2;
            int g2 = gm + 8;
            uint32_t a1 = plane + (uint32_t)g2 * 256 + (((col >> 3) ^ (g2 & 7)) << 4) + (col & 7) * 2;
            *(__half2*)(smem + a0) = __floats2half2_rn(acc[mt][nt][0], acc[mt][nt][1]);
            *(__half2*)(smem + a1) = __floats2half2_rn(acc[mt][nt][2], acc[mt][nt][3]);
        }
    }
}

// P-warp park: recompute softmax for ONE head hh, write fp16 plane
__device__ __forceinline__ void park_head(char* smem, uint32_t plane, int sp,
                                          int lane, int wid, int hh) {
    float slj_h[4];
#pragma unroll
    for (int u = 0; u < 4; u++)
        slj_h[u] = pick4(*(const float4*)&g_sl[(sp * 128 + lane + 32 * u) * 4], hh);
    for (int it = 0; it < 16; it++) {
        int i = it * 8 + wid;
        float sri = pick4(*(const float4*)&g_sr[(sp * 128 + i) * 4], hh);
        float e[4];
#pragma unroll
        for (int u = 0; u < 4; u++) {
            int j = lane + 32 * u;
            float x = sri + slj_h[u];
            x = (x >= 0.f) ? x : 0.2f * x;
            e[u] = (j == i) ? -3.0e38f : x;
        }
        float m = fmaxf(fmaxf(e[0], e[1]), fmaxf(e[2], e[3]));
        for (int o = 16; o; o >>= 1) m = fmaxf(m, __shfl_xor_sync(0xffffffffu, m, o));
        float s = 0.f;
#pragma unroll
        for (int u = 0; u < 4; u++) {
            int j = lane + 32 * u;
            float p = (j == i) ? 0.f : __expf(e[u] - m);
            e[u] = p;
            s += p;
        }
        for (int o = 16; o; o >>= 1) s += __shfl_xor_sync(0xffffffffu, s, o);
        float inv = 1.0f / s;
#pragma unroll
        for (int u = 0; u < 4; u++) {
            int j = lane + 32 * u;
            uint32_t ad = plane + (uint32_t)i * 256 + (((j >> 3) ^ (i & 7)) << 4) + (j & 7) * 2;
            *(__half*)(smem + ad) = __float2half_rn(e[u] * inv);
        }
    }
}

__global__ void __launch_bounds__(512) k_fused(const float* __restrict__ h,
                                               float* __restrict__ out1,
                                               float* __restrict__ out2) {
    extern __shared__ char smem[];
    uint32_t sb = smem_u32(smem);
    int tid = threadIdx.x;
    int lane = tid & 31, wid = tid >> 5;      // 16 warps
    int sp = blockIdx.x;
    bool isP = wid < 8;
    int cw = wid - 8;                         // C warp id 0..7
    int wm = wid & 3, wn = (wid >> 2) & 1;    // P tile coords (32m x 64n)
    int cm = cw & 3, cn = cw >> 1 & 1;        // C tile coords
    cn = cw >> 2;                             // (fix: cw 0..7 -> cm 0..3, cn 0..1)

    // ---- stage 0: fill h tile; P prefetches W0 ----
    if (isP) fill_w_sw(sb + F_W0, g_wth, tid);
    for (int idx = tid; idx < 4096; idx += 512) {     // 128 rows x 32 float4
        int row = idx >> 5, c4 = idx & 31;
        float4 v = *(const float4*)&h[((size_t)row * SPN + sp) * FF + c4 * 4];
        uint32_t off = F_HT + (uint32_t)row * 256 + (((c4 >> 1) ^ (row & 7)) << 4) + (c4 & 1) * 8;
        *(uint32_t*)(smem + off) = h2_u32(__floats2half2_rn(v.x, v.y));
        *(uint32_t*)(smem + off + 4) = h2_u32(__floats2half2_rn(v.z, v.w));
    }
    __syncthreads();

    float acc[2][8][4];
#pragma unroll
    for (int i = 0; i < 2; i++)
#pragma unroll
        for (int j = 0; j < 8; j++)
#pragma unroll
            for (int q = 0; q < 4; q++) acc[i][j][q] = 0.f;

    // ---- stage 1: P -> MMA1(h0)->G0 ; C -> full softmax (out2 + park h0,h1) ----
    if (isP) {
        fill_w_sw(sb + F_W1, g_wth + 16384, tid);
        cpwait<1>();
        mma_tile(sb + F_W0, sb + F_HT, acc, lane, wm * 32, wn * 64);
        store_g(smem, F_G0, acc, lane, wm, wn);
    } else {
        float4 slj[4];
#pragma unroll
        for (int u = 0; u < 4; u++)
            slj[u] = *(const float4*)&g_sl[(sp * 128 + lane + 32 * u) * 4];
        for (int it = 0; it < 16; it++) {
            int i = it * 8 + cw;
            float4 sri = *(const float4*)&g_sr[(sp * 128 + i) * 4];
            float e[4][4];
#pragma unroll
            for (int u = 0; u < 4; u++) {
                int j = lane + 32 * u;
                float v[4] = {sri.x + slj[u].x, sri.y + slj[u].y,
                              sri.z + slj[u].z, sri.w + slj[u].w};
#pragma unroll
                for (int hh = 0; hh < 4; hh++) {
                    float x = v[hh];
                    x = (x >= 0.f) ? x : 0.2f * x;
                    e[u][hh] = (j == i) ? -3.0e38f : x;
                }
            }
#pragma unroll
            for (int hh = 0; hh < 4; hh++) {
                float m = fmaxf(fmaxf(e[0][hh], e[1][hh]), fmaxf(e[2][hh], e[3][hh]));
                for (int o = 16; o; o >>= 1) m = fmaxf(m, __shfl_xor_sync(0xffffffffu, m, o));
                float s = 0.f;
#pragma unroll
                for (int u = 0; u < 4; u++) {
                    int j = lane + 32 * u;
                    float p = (j == i) ? 0.f : __expf(e[u][hh] - m);
                    e[u][hh] = p;
                    s += p;
                }
                for (int o = 16; o; o >>= 1) s += __shfl_xor_sync(0xffffffffu, s, o);
                float inv = 1.0f / s;
#pragma unroll
                for (int u = 0; u < 4; u++) e[u][hh] *= inv;
            }
            float* base = out2 + (size_t)sp * 65536 + (size_t)i * 512;
#pragma unroll
            for (int u = 0; u < 4; u++) {
                int j = lane + 32 * u;
                *(float4*)&base[j * 4] = make_float4(e[u][0], e[u][1], e[u][2], e[u][3]);
            }
#pragma unroll
            for (int k2 = 0; k2 < 2; k2++) {
                uint32_t plane = k2 ? F_A1 : F_A0;
#pragma unroll
                for (int u = 0; u < 4; u++) {
                    int j = lane + 32 * u;
                    uint32_t ad = plane + (uint32_t)i * 256 + (((j >> 3) ^ (i & 7)) << 4) + (j & 7) * 2;
                    *(__half*)(smem + ad) = __float2half_rn(e[u][k2]);
                }
            }
        }
    }
    __syncthreads();

    // ---- stage 2: P -> MMA1(h1)->G1 ; C -> MMA2(h0) ----
    if (isP) {
        fill_w_sw(sb + F_W0, g_wth + 2 * 16384, tid);
        cpwait<1>();
#pragma unroll
        for (int i = 0; i < 2; i++)
#pragma unroll
            for (int j = 0; j < 8; j++)
#pragma unroll
                for (int q = 0; q < 4; q++) acc[i][j][q] = 0.f;
        mma_tile(sb + F_W1, sb + F_HT, acc, lane, wm * 32, wn * 64);
        store_g(smem, F_G1, acc, lane, wm, wn);
    } else {
        mma_tile(sb + F_A0, sb + F_G0, acc, lane, cm * 32, cn * 64);
    }
    __syncthreads();

    // ---- stage 3: P -> MMA1(h2)->G0 + park h2->A0 ; C -> MMA2(h1) ----
    if (isP) {
        fill_w_sw(sb + F_W1, g_wth + 3 * 16384, tid);
        cpwait<1>();
        float a1[2][8][4];
#pragma unroll
        for (int i = 0; i < 2; i++)
#pragma unroll
            for (int j = 0; j < 8; j++)
#pragma unroll
                for (int q = 0; q < 4; q++) a1[i][j][q] = 0.f;
        mma_tile(sb + F_W0, sb + F_HT, a1, lane, wm * 32, wn * 64);
        store_g(smem, F_G0, a1, lane, wm, wn);
        park_head(smem, F_A0, sp, lane, wid, 2);
    } else {
        mma_tile(sb + F_A1, sb + F_G1, acc, lane, cm * 32, cn * 64);
    }
    __syncthreads();

    // ---- stage 4: P -> MMA1(h3)->G1 + park h3->A1 ; C -> MMA2(h2) ----
    if (isP) {
        cpwait<0>();
        float a1[2][8][4];
#pragma unroll
        for (int i = 0; i < 2; i++)
#pragma unroll
            for (int j = 0; j < 8; j++)
#pragma unroll
                for (int q = 0; q < 4; q++) a1[i][j][q] = 0.f;
        mma_tile(sb + F_W1, sb + F_HT, a1, lane, wm * 32, wn * 64);
        store_g(smem, F_G1, a1, lane, wm, wn);
        park_head(smem, F_A1, sp, lane, wid, 3);
    } else {
        mma_tile(sb + F_A0, sb + F_G0, acc, lane, cm * 32, cn * 64);
    }
    __syncthreads();

    // ---- stage 5: C -> MMA2(h3); epilogue ----
    if (!isP) {
        mma_tile(sb + F_A1, sb + F_G1, acc, lane, cm * 32, cn * 64);
#pragma unroll
        for (int mt = 0; mt < 2; mt++) {
#pragma unroll
            for (int nt = 0; nt < 8; nt++) {
                int i0 = cm * 32 + mt * 16 + (lane >> 2);
                int d0 = cn * 64 + nt * 8 + (lane & 3) * 2;
                float2 v0 = make_float2(acc[mt][nt][0] * 0.25f, acc[mt][nt][1] * 0.25f);
                float2 v1 = make_float2(acc[mt][nt][2] * 0.25f, acc[mt][nt][3] * 0.25f);
                *(float2*)&out1[((size_t)i0 * SPN + sp) * 128 + d0] = v0;
                *(float2*)&out1[((size_t)(i0 + 8) * SPN + sp) * 128 + d0] = v1;
            }
        }
    }
}

// ============================================================
extern "C" void kernel_launch(void* const* d_in, const int* in_sizes, int n_in,
                              void* d_out, int out_size) {
    const float* h  = (const float*)d_in[0];
    const float* Wl = (const float*)d_in[1];
    const float* Wr = (const float*)d_in[2];
    const float* wa = (const float*)d_in[3];

    float* out1 = (float*)d_out;                 // attn_res: A*S*P*D
    float* out2 = out1 + (size_t)AA * SPN * DD;  // a: S*P*A*A*H

    // Unconditional (no static guards): immediate, idempotent, capture-safe.
    cudaFuncSetAttribute(k_fused, cudaFuncAttributeMaxDynamicSharedMemorySize, F_SIZE);

    k_u<<<1, 512>>>(Wl, Wr, wa);
    k_s<<<RR / 8, 256>>>(h);
    k_split_w<<<(NNW * FF) / 256, 256>>>(Wr);
    k_fused<<<SPN, 512, F_SIZE>>>(h, out1, out2);
}

// round 17
// speedup vs baseline: 1.8141x; 1.8141x over previous
#include <cuda_runtime.h>
#include <cuda_fp16.h>
#include <cstdint>

// Problem constants
#define AA   128
#define SPN  1024
#define FF   128
#define HH   4
#define DD   128
#define NNW  512
#define RR   131072

// ------------------------------------------------------------------
// Scratch (static device globals — allocation-rule safe)
// ------------------------------------------------------------------
__device__ __align__(16) __half g_wth[NNW * FF];                      // W_r^T fp16: [n_g][f]
__device__ __align__(16) float g_sl[RR * HH];
__device__ __align__(16) float g_sr[RR * HH];
__device__ __align__(16) float g_ul[FF * HH];
__device__ __align__(16) float g_ur[FF * HH];

// ------------------------------------------------------------------
// PTX helpers
// ------------------------------------------------------------------
__device__ __forceinline__ uint32_t smem_u32(const void* p) {
    uint32_t a;
    asm("{ .reg .u64 t; cvta.to.shared.u64 t, %1; cvt.u32.u64 %0, t; }" : "=r"(a) : "l"(p));
    return a;
}
__device__ __forceinline__ void ldsm4(uint32_t* r, uint32_t addr) {
    asm volatile("ldmatrix.sync.aligned.m8n8.x4.shared.b16 {%0,%1,%2,%3}, [%4];"
                 : "=r"(r[0]), "=r"(r[1]), "=r"(r[2]), "=r"(r[3]) : "r"(addr));
}
__device__ __forceinline__ void ldsm2(uint32_t* r, uint32_t addr) {
    asm volatile("ldmatrix.sync.aligned.m8n8.x2.shared.b16 {%0,%1}, [%2];"
                 : "=r"(r[0]), "=r"(r[1]) : "r"(addr));
}
__device__ __forceinline__ void mma16816(float* c, const uint32_t* a, const uint32_t* b) {
    asm volatile("mma.sync.aligned.m16n8k16.row.col.f32.f16.f16.f32 "
                 "{%0,%1,%2,%3}, {%4,%5,%6,%7}, {%8,%9}, {%0,%1,%2,%3};"
                 : "+f"(c[0]), "+f"(c[1]), "+f"(c[2]), "+f"(c[3])
                 : "r"(a[0]), "r"(a[1]), "r"(a[2]), "r"(a[3]), "r"(b[0]), "r"(b[1]));
}
__device__ __forceinline__ void cpasync16(uint32_t dst, const void* src) {
    asm volatile("cp.async.cg.shared.global [%0], [%1], 16;" :: "r"(dst), "l"(src));
}
__device__ __forceinline__ void cpcommit() { asm volatile("cp.async.commit_group;"); }
template<int N> __device__ __forceinline__ void cpwait() {
    asm volatile("cp.async.wait_group %0;" :: "n"(N));
}
__device__ __forceinline__ uint32_t h2_u32(__half2 v) {
    return *reinterpret_cast<uint32_t*>(&v);
}
// swizzled address of 16B chunk ch (0..15) in row r (256B rows, XOR row&7)
__device__ __forceinline__ uint32_t sw16(int r, int ch) {
    return (uint32_t)(r * 256 + ((ch ^ (r & 7)) << 4));
}
// swizzled byte address of half element (r, col)
__device__ __forceinline__ uint32_t swh(int r, int col) {
    return (uint32_t)(r * 256 + (((col >> 3) ^ (r & 7)) << 4) + (col & 7) * 2);
}

// ============================================================
// K1: fold w_attn into W_l / W_r per head
// ============================================================
__global__ void k_u(const float* __restrict__ Wl, const float* __restrict__ Wr,
                    const float* __restrict__ wa) {
    __shared__ float w[2 * DD];
    int t = threadIdx.x;               // 512 threads
    if (t < 2 * DD) w[t] = wa[t];
    __syncthreads();
    int f = t >> 2, hh = t & 3;
    const float* pl = Wl + (size_t)f * NNW + hh * DD;
    const float* pr = Wr + (size_t)f * NNW + hh * DD;
    float sl = 0.f, sr = 0.f;
#pragma unroll 4
    for (int d = 0; d < DD; d++) {
        sl = fmaf(pl[d], w[d], sl);
        sr = fmaf(pr[d], w[DD + d], sr);
    }
    g_ul[f * HH + hh] = sl;
    g_ur[f * HH + hh] = sr;
}

// ============================================================
// K2: transpose W_r to fp16: g_wth[n][f] = fp16(W_r[f][n])
// ============================================================
__global__ void __launch_bounds__(256) k_split_w(const float* __restrict__ Wr) {
    int t = blockIdx.x * 256 + threadIdx.x;            // < NNW*FF = 65536
    int f = t & 127, n = t >> 7;
    g_wth[t] = __float2half_rn(Wr[(size_t)f * NNW + n]);
}

// ============================================================
// K3: FUSED per-sp kernel (512 threads, all warps do everything):
//   fill h-tile fp16 + compute exact-fp32 s_l/s_r inline (k_s fused)
//   ONE softmax pass: exact fp32 'a' -> out2, park 4 fp16 head planes
//   per head: MMA1 (g in SMEM) -> MMA2 accumulate; W(h+1) cp.async
//   overlapped with MMA2(h).
// ============================================================
// 7 swizzled planes, 256B row stride, 32KB each:
#define F_HT   0
#define F_WT   32768
#define F_GT   65536
#define F_A0   98304      // A planes: F_A0 + hh*32768
#define F_SIZE 229376

// cp.async fill [128][128]-half tile into swizzled plane (512 threads)
__device__ __forceinline__ void fill_w_sw(uint32_t dbuf, const __half* src, int t) {
#pragma unroll
    for (int q = 0; q < 4; q++) {
        int idx = t + q * 512;            // 0..2047
        int r = idx >> 4, c = idx & 15;
        cpasync16(dbuf + sw16(r, c), src + r * 128 + c * 8);
    }
    cpcommit();
}

// one 128x128x128 tile GEMM, warp tile 32(m) x 32(n)
__device__ __forceinline__ void mma_tile(uint32_t sbA, uint32_t sbB,
                                         float acc[2][4][4], int lane,
                                         int base_m, int base_n) {
#pragma unroll
    for (int ks = 0; ks < 8; ks++) {
        int chA = 2 * ks + (lane >> 4);
        int chB = 2 * ks + ((lane >> 3) & 1);
        uint32_t bh[4][2];
#pragma unroll
        for (int nt = 0; nt < 4; nt++) {
            int r = base_n + nt * 8 + (lane & 7);
            ldsm2(bh[nt], sbB + sw16(r, chB));
        }
#pragma unroll
        for (int mt = 0; mt < 2; mt++) {
            int r = base_m + mt * 16 + (lane & 15);
            uint32_t ah[4];
            ldsm4(ah, sbA + sw16(r, chA));
#pragma unroll
            for (int nt = 0; nt < 4; nt++) mma16816(acc[mt][nt], ah, bh[nt]);
        }
    }
}

__global__ void __launch_bounds__(512) k_fused(const float* __restrict__ h,
                                               float* __restrict__ out1,
                                               float* __restrict__ out2) {
    extern __shared__ char smem[];
    uint32_t sb = smem_u32(smem);
    int tid = threadIdx.x;
    int lane = tid & 31, wid = tid >> 5;      // 16 warps
    int wm = wid & 3, wn = wid >> 2;          // warp tile 32(m) x 32(n)
    int sp = blockIdx.x;

    // prefetch W head 0
    fill_w_sw(sb + F_WT, g_wth, tid);

    // ---- fill h tile (fp32->fp16 swizzled) + fused s_l/s_r ----
    {
        // per-lane u columns: f = lane*4 + q
        float4 ulq[4], urq[4];
#pragma unroll
        for (int q = 0; q < 4; q++) {
            ulq[q] = *(const float4*)&g_ul[(lane * 4 + q) * 4];
            urq[q] = *(const float4*)&g_ur[(lane * 4 + q) * 4];
        }
#pragma unroll
        for (int k = 0; k < 8; k++) {
            int row = wid + 16 * k;
            float4 v = *(const float4*)&h[((size_t)row * SPN + sp) * FF + lane * 4];
            uint32_t off = F_HT + (uint32_t)row * 256 +
                           (((lane >> 1) ^ (row & 7)) << 4) + (lane & 1) * 8;
            *(uint32_t*)(smem + off) = h2_u32(__floats2half2_rn(v.x, v.y));
            *(uint32_t*)(smem + off + 4) = h2_u32(__floats2half2_rn(v.z, v.w));
            // s partial: dot of this lane's 4 f-values with u columns
            float sl[4], sr[4];
#pragma unroll
            for (int hh = 0; hh < 4; hh++) {
                float* pl = (float*)&ulq[0];
                float* pr = (float*)&urq[0];
                sl[hh] = v.x * pl[hh] + v.y * ((float*)&ulq[1])[hh]
                       + v.z * ((float*)&ulq[2])[hh] + v.w * ((float*)&ulq[3])[hh];
                sr[hh] = v.x * pr[hh] + v.y * ((float*)&urq[1])[hh]
                       + v.z * ((float*)&urq[2])[hh] + v.w * ((float*)&urq[3])[hh];
            }
#pragma unroll
            for (int hh = 0; hh < 4; hh++) {
                for (int o = 16; o; o >>= 1) {
                    sl[hh] += __shfl_xor_sync(0xffffffffu, sl[hh], o);
                    sr[hh] += __shfl_xor_sync(0xffffffffu, sr[hh], o);
                }
            }
            if (lane == 0) {
                *(float4*)&g_sl[(sp * 128 + row) * 4] = make_float4(sl[0], sl[1], sl[2], sl[3]);
                *(float4*)&g_sr[(sp * 128 + row) * 4] = make_float4(sr[0], sr[1], sr[2], sr[3]);
            }
        }
    }
    __syncthreads();   // h tile + s visible to all warps

    // ---- softmax, ONE pass: fp32 'a' -> out2; park 4 fp16 planes ----
    {
        float4 slj[4];
#pragma unroll
        for (int u = 0; u < 4; u++)
            slj[u] = *(const float4*)&g_sl[(sp * 128 + lane + 32 * u) * 4];

        for (int it = 0; it < 8; it++) {
            int i = it * 16 + wid;
            float4 sri = *(const float4*)&g_sr[(sp * 128 + i) * 4];
            float e[4][4];
#pragma unroll
            for (int u = 0; u < 4; u++) {
                int j = lane + 32 * u;
                float v[4] = {sri.x + slj[u].x, sri.y + slj[u].y,
                              sri.z + slj[u].z, sri.w + slj[u].w};
#pragma unroll
                for (int hh = 0; hh < 4; hh++) {
                    float x = v[hh];
                    x = (x >= 0.f) ? x : 0.2f * x;
                    e[u][hh] = (j == i) ? -3.0e38f : x;
                }
            }
#pragma unroll
            for (int hh = 0; hh < 4; hh++) {
                float m = fmaxf(fmaxf(e[0][hh], e[1][hh]), fmaxf(e[2][hh], e[3][hh]));
                for (int o = 16; o; o >>= 1) m = fmaxf(m, __shfl_xor_sync(0xffffffffu, m, o));
                float s = 0.f;
#pragma unroll
                for (int u = 0; u < 4; u++) {
                    int j = lane + 32 * u;
                    float p = (j == i) ? 0.f : __expf(e[u][hh] - m);
                    e[u][hh] = p;
                    s += p;
                }
                for (int o = 16; o; o >>= 1) s += __shfl_xor_sync(0xffffffffu, s, o);
                float inv = 1.0f / s;
#pragma unroll
                for (int u = 0; u < 4; u++) e[u][hh] *= inv;
            }
            // exact fp32 'a', coalesced float4
            float* base = out2 + (size_t)sp * 65536 + (size_t)i * 512;
#pragma unroll
            for (int u = 0; u < 4; u++) {
                int j = lane + 32 * u;
                *(float4*)&base[j * 4] = make_float4(e[u][0], e[u][1], e[u][2], e[u][3]);
            }
            // park all 4 heads as fp16 planes [i][j]
#pragma unroll
            for (int hh = 0; hh < 4; hh++) {
                uint32_t plane = F_A0 + hh * 32768;
#pragma unroll
                for (int u = 0; u < 4; u++) {
                    int j = lane + 32 * u;
                    *(__half*)(smem + plane + swh(i, j)) = __float2half_rn(e[u][hh]);
                }
            }
        }
    }

    // ---- per-head: MMA1 -> g (SMEM) -> MMA2 accumulate ----
    float acc2[2][4][4];
#pragma unroll
    for (int i = 0; i < 2; i++)
#pragma unroll
        for (int j = 0; j < 4; j++)
#pragma unroll
            for (int q = 0; q < 4; q++) acc2[i][j][q] = 0.f;

    for (int hh = 0; hh < 4; hh++) {
        cpwait<0>();
        __syncthreads();   // W(hh) ready+visible; GT free (prev MMA2 done)

        // MMA1: g_h[n][a] = W_h @ h^T
        float acc1[2][4][4];
#pragma unroll
        for (int i = 0; i < 2; i++)
#pragma unroll
            for (int j = 0; j < 4; j++)
#pragma unroll
                for (int q = 0; q < 4; q++) acc1[i][j][q] = 0.f;
        mma_tile(sb + F_WT, sb + F_HT, acc1, lane, wm * 32, wn * 32);

        // store g to swizzled GT plane (fp16): rows d, cols j
#pragma unroll
        for (int mt = 0; mt < 2; mt++) {
#pragma unroll
            for (int nt = 0; nt < 4; nt++) {
                int gm = wm * 32 + mt * 16 + (lane >> 2);
                int col = wn * 32 + nt * 8 + (lane & 3) * 2;
                *(__half2*)(smem + F_GT + swh(gm, col)) =
                    __floats2half2_rn(acc1[mt][nt][0], acc1[mt][nt][1]);
                *(__half2*)(smem + F_GT + swh(gm + 8, col)) =
                    __floats2half2_rn(acc1[mt][nt][2], acc1[mt][nt][3]);
            }
        }
        __syncthreads();   // GT complete; WT free to refill

        if (hh < 3) fill_w_sw(sb + F_WT, g_wth + (hh + 1) * 16384, tid);

        // MMA2: acc2[i][d] += a_hh @ g_h^T  (overlaps W(hh+1) DMA)
        mma_tile(sb + F_A0 + hh * 32768, sb + F_GT, acc2, lane, wm * 32, wn * 32);
    }

    // epilogue: x0.25, output layout (A, S, P, D)
#pragma unroll
    for (int mt = 0; mt < 2; mt++) {
#pragma unroll
        for (int nt = 0; nt < 4; nt++) {
            int i0 = wm * 32 + mt * 16 + (lane >> 2);
            int d0 = wn * 32 + nt * 8 + (lane & 3) * 2;
            float2 v0 = make_float2(acc2[mt][nt][0] * 0.25f, acc2[mt][nt][1] * 0.25f);
            float2 v1 = make_float2(acc2[mt][nt][2] * 0.25f, acc2[mt][nt][3] * 0.25f);
            *(float2*)&out1[((size_t)i0 * SPN + sp) * 128 + d0] = v0;
            *(float2*)&out1[((size_t)(i0 + 8) * SPN + sp) * 128 + d0] = v1;
        }
    }
}

// ============================================================
extern "C" void kernel_launch(void* const* d_in, const int* in_sizes, int n_in,
                              void* d_out, int out_size) {
    const float* h  = (const float*)d_in[0];
    const float* Wl = (const float*)d_in[1];
    const float* Wr = (const float*)d_in[2];
    const float* wa = (const float*)d_in[3];

    float* out1 = (float*)d_out;                 // attn_res: A*S*P*D
    float* out2 = out1 + (size_t)AA * SPN * DD;  // a: S*P*A*A*H

    // Unconditional (no static guards): immediate, idempotent, capture-safe.
    cudaFuncSetAttribute(k_fused, cudaFuncAttributeMaxDynamicSharedMemorySize, F_SIZE);

    k_u<<<1, 512>>>(Wl, Wr, wa);
    k_split_w<<<(NNW * FF) / 256, 256>>>(Wr);
    k_fused<<<SPN, 512, F_SIZE>>>(h, out1, out2);
}